// round 10
// baseline (speedup 1.0000x reference)
#include <cuda_runtime.h>
#include <math.h>

// GeodesicLoss: reference initializes velocity to zero, so the geodesic ODE
// acc = -Gamma v v is identically zero for all 10 steps -> traj == outputs.
// Result is exactly mean_b || outputs_b - targets_b ||_2.
// Pure streaming reduction over 128 MiB -> DRAM-bound.
//
// R10: stream kernel = R1's measured-best tail-free layout (16384x256, one
// float4-pair/thread, plain STG partial, ~22.3us). Block 0 also zeroes
// out[0] (graph edge orders it before the reduce -> no init node).
// Reduce kernel = 16 blocks x 256 threads (one float4/thread over all 16384
// partials), per-block tree, then fire-and-forget red.global.add.f32 into
// out[0]. 16 SMs fetch the DRAM-resident partials in parallel -> ~0.5us
// instead of R8/R9's 4.3-4.9us single-SM latency-bound reduce.

#define B_ROWS   524288
#define D_DIM    32
#define THREADS  256
#define NBLOCKS  16384       // NBLOCKS*THREADS = 4M threads = B_ROWS*8

#define RBLOCKS  16          // reduce kernel blocks
#define RTHREADS 256         // RBLOCKS*RTHREADS*4 == NBLOCKS

__device__ float g_partials[NBLOCKS];

__global__ __launch_bounds__(THREADS)
void geodesic_loss_stream_kernel(const float* __restrict__ outputs,
                                 const float* __restrict__ targets,
                                 float* __restrict__ out) {
    const int tid = blockIdx.x * THREADS + threadIdx.x;
    const int row = tid >> 3;              // 8 lanes per row
    const int sub = threadIdx.x & 7;       // which float4 of the row

    // Zero the accumulator for this replay; the graph edge orders this
    // before the reduce kernel's atomics. (out is poisoned by the harness.)
    if (tid == 0)
        out[0] = 0.0f;

    const float4* __restrict__ o4 = reinterpret_cast<const float4*>(outputs);
    const float4* __restrict__ t4 = reinterpret_cast<const float4*>(targets);

    const int idx = row * (D_DIM / 4) + sub;
    float4 a = o4[idx];
    float4 b = t4[idx];

    float dx = a.x - b.x;
    float dy = a.y - b.y;
    float dz = a.z - b.z;
    float dw = a.w - b.w;
    float s = dx * dx + dy * dy + dz * dz + dw * dw;

    // Reduce the 8 lanes covering this row (butterfly)
    s += __shfl_xor_sync(0xFFFFFFFFu, s, 1);
    s += __shfl_xor_sync(0xFFFFFFFFu, s, 2);
    s += __shfl_xor_sync(0xFFFFFFFFu, s, 4);

    // One representative lane per row contributes sqrt(row_sum)
    float v = (sub == 0) ? sqrtf(s) : 0.0f;

    // Sum the 4 row-norms held in this warp (lanes 0,8,16,24)
    v += __shfl_xor_sync(0xFFFFFFFFu, v, 8);
    v += __shfl_xor_sync(0xFFFFFFFFu, v, 16);

    __shared__ float wsum[THREADS / 32];   // 8 warp sums
    if ((threadIdx.x & 31) == 0)
        wsum[threadIdx.x >> 5] = v;
    __syncthreads();

    if (threadIdx.x == 0) {
        float bsum = 0.0f;
        #pragma unroll
        for (int i = 0; i < THREADS / 32; i++)
            bsum += wsum[i];
        g_partials[blockIdx.x] = bsum;   // plain store: no CTA-exit atomic wait
    }
}

// Parallel final reduce: 16 blocks x 256 threads, one float4 per thread.
// Per-block tree, then one fire-and-forget red.global.add per block.
__global__ __launch_bounds__(RTHREADS)
void geodesic_final_reduce_kernel(float* __restrict__ out) {
    const float4* __restrict__ p4 = reinterpret_cast<const float4*>(g_partials);

    float4 v = __ldcg(&p4[blockIdx.x * RTHREADS + threadIdx.x]);
    float s = (v.x + v.y) + (v.z + v.w);

    s += __shfl_xor_sync(0xFFFFFFFFu, s, 1);
    s += __shfl_xor_sync(0xFFFFFFFFu, s, 2);
    s += __shfl_xor_sync(0xFFFFFFFFu, s, 4);
    s += __shfl_xor_sync(0xFFFFFFFFu, s, 8);
    s += __shfl_xor_sync(0xFFFFFFFFu, s, 16);

    __shared__ float wsum[RTHREADS / 32];
    if ((threadIdx.x & 31) == 0)
        wsum[threadIdx.x >> 5] = s;
    __syncthreads();

    if (threadIdx.x == 0) {
        float bsum = 0.0f;
        #pragma unroll
        for (int i = 0; i < RTHREADS / 32; i++)
            bsum += wsum[i];
        bsum *= (1.0f / (float)B_ROWS);
        asm volatile("red.global.add.f32 [%0], %1;"
                     :: "l"(out), "f"(bsum) : "memory");
    }
}

extern "C" void kernel_launch(void* const* d_in, const int* in_sizes, int n_in,
                              void* d_out, int out_size) {
    const float* outputs = (const float*)d_in[0];
    const float* targets = (const float*)d_in[1];
    // d_in[2] (christoffel_symbols) is mathematically dead: vel starts at 0.
    float* out = (float*)d_out;

    geodesic_loss_stream_kernel<<<NBLOCKS, THREADS>>>(outputs, targets, out);
    geodesic_final_reduce_kernel<<<RBLOCKS, RTHREADS>>>(out);
}

// round 11
// speedup vs baseline: 1.0083x; 1.0083x over previous
#include <cuda_runtime.h>
#include <math.h>

// GeodesicLoss: reference initializes velocity to zero, so the geodesic ODE
// acc = -Gamma v v is identically zero for all 10 steps -> traj == outputs.
// Result is exactly mean_b || outputs_b - targets_b ||_2.
// Pure streaming reduction over 128 MiB -> DRAM-bound.
//
// R11: the two-node path has a fixed ~4.6us second-node floor (measured
// invariant across grid=1/16/PDL), so fuse -- but the fused-tail atomic tax
// scales with block count (16384 -> ~11us, 4096 -> ~3us). Use 2048 blocks
// with a software-pipelined 8-iteration loop (double-buffered prefetch whose
// live range crosses the compute, forcing ptxas to keep loads in flight).
// Tail: plain partial store + 1 atomicAdd per block (2048 total), winner
// block reduces 512 float4 in fixed order -> deterministic; counter
// self-resets for graph replay.

#define B_ROWS   524288
#define D_DIM    32
#define THREADS  256
#define NBLOCKS  2048
#define ITERS    8
#define ROWS_PER_ITER  32                       // THREADS/8
#define ROWS_PER_BLOCK (ROWS_PER_ITER * ITERS)  // 256; NBLOCKS*256 = B_ROWS
#define F4_PER_ITER    (ROWS_PER_ITER * (D_DIM / 4))   // 256 float4 = 4KB

__device__ float        g_partials[NBLOCKS];
__device__ unsigned int g_done_count = 0;

__global__ __launch_bounds__(THREADS)
void geodesic_loss_fused_kernel(const float* __restrict__ outputs,
                                const float* __restrict__ targets,
                                float* __restrict__ out) {
    const int sub      = threadIdx.x & 7;       // which float4 of the row
    const int row_in_b = threadIdx.x >> 3;      // row slot within iter-slice
    const int base_row = blockIdx.x * ROWS_PER_BLOCK;

    const float4* __restrict__ o4 = reinterpret_cast<const float4*>(outputs);
    const float4* __restrict__ t4 = reinterpret_cast<const float4*>(targets);

    const int idx = (base_row + row_in_b) * (D_DIM / 4) + sub;

    // Software pipeline: current pair (a,b) + prefetched next pair (an,bn).
    float4 a = o4[idx];
    float4 b = t4[idx];

    float acc = 0.0f;

    #pragma unroll
    for (int it = 0; it < ITERS; it++) {
        // Prefetch next iteration BEFORE the dependent compute chain; the
        // live range of (an,bn) crosses the shuffles, so ptxas must keep
        // these loads in flight (real MLP, not front-batch that gets
        // re-serialized).
        const int nidx = idx + (it + 1 < ITERS ? (it + 1) : it) * F4_PER_ITER;
        float4 an = o4[nidx];
        float4 bn = t4[nidx];

        float dx = a.x - b.x;
        float dy = a.y - b.y;
        float dz = a.z - b.z;
        float dw = a.w - b.w;
        float s = dx * dx + dy * dy + dz * dz + dw * dw;

        // Reduce the 8 lanes covering this row
        s += __shfl_xor_sync(0xFFFFFFFFu, s, 1);
        s += __shfl_xor_sync(0xFFFFFFFFu, s, 2);
        s += __shfl_xor_sync(0xFFFFFFFFu, s, 4);

        if (sub == 0)
            acc += sqrtf(s);

        a = an;
        b = bn;
    }

    // Sum the 4 per-row accumulators in this warp (lanes 0,8,16,24)
    acc += __shfl_xor_sync(0xFFFFFFFFu, acc, 8);
    acc += __shfl_xor_sync(0xFFFFFFFFu, acc, 16);

    __shared__ float wsum[THREADS / 32];   // 8 warp sums
    if ((threadIdx.x & 31) == 0)
        wsum[threadIdx.x >> 5] = acc;
    __syncthreads();

    __shared__ bool s_is_last;
    if (threadIdx.x == 0) {
        float bsum = 0.0f;
        #pragma unroll
        for (int i = 0; i < THREADS / 32; i++)
            bsum += wsum[i];

        // Partial straight to L2, then release-scoped counter bump
        // (orders the store; no gpu-scope fence / L1 flush).
        asm volatile("st.global.cg.f32 [%0], %1;"
                     :: "l"(&g_partials[blockIdx.x]), "f"(bsum) : "memory");
        unsigned int prev;
        asm volatile("atom.release.gpu.global.add.u32 %0, [%1], 1;"
                     : "=r"(prev) : "l"(&g_done_count) : "memory");
        s_is_last = (prev == NBLOCKS - 1);
    }
    __syncthreads();

    if (s_is_last) {
        // Final reduce over 2048 partials (8 KB, L2-resident): 256 threads
        // x 2 float4 __ldcg loads, fixed order -> deterministic.
        const float4* __restrict__ p4 =
            reinterpret_cast<const float4*>(g_partials);
        float4 v0 = __ldcg(&p4[threadIdx.x]);
        float4 v1 = __ldcg(&p4[threadIdx.x + THREADS]);
        float s2 = ((v0.x + v0.y) + (v0.z + v0.w))
                 + ((v1.x + v1.y) + (v1.z + v1.w));

        s2 += __shfl_xor_sync(0xFFFFFFFFu, s2, 1);
        s2 += __shfl_xor_sync(0xFFFFFFFFu, s2, 2);
        s2 += __shfl_xor_sync(0xFFFFFFFFu, s2, 4);
        s2 += __shfl_xor_sync(0xFFFFFFFFu, s2, 8);
        s2 += __shfl_xor_sync(0xFFFFFFFFu, s2, 16);

        __shared__ float fsum[THREADS / 32];
        if ((threadIdx.x & 31) == 0)
            fsum[threadIdx.x >> 5] = s2;
        __syncthreads();

        if (threadIdx.x == 0) {
            float tot = 0.0f;
            #pragma unroll
            for (int i = 0; i < THREADS / 32; i++)
                tot += fsum[i];
            out[0] = tot * (1.0f / (float)B_ROWS);
            g_done_count = 0;   // reset for next graph replay
        }
    }
}

extern "C" void kernel_launch(void* const* d_in, const int* in_sizes, int n_in,
                              void* d_out, int out_size) {
    const float* outputs = (const float*)d_in[0];
    const float* targets = (const float*)d_in[1];
    // d_in[2] (christoffel_symbols) is mathematically dead: vel starts at 0.
    float* out = (float*)d_out;

    geodesic_loss_fused_kernel<<<NBLOCKS, THREADS>>>(outputs, targets, out);
}